// round 16
// baseline (speedup 1.0000x reference)
#include <cuda_runtime.h>
#include <cuda_bf16.h>

#define PMAX 118
#define NMAX 236
#define D 32
#define TBLN (PMAX * NMAX)          // 27848 pairs
#define WBLKS 96
#define NWARPS (WBLKS * 4)
#define FULL 0xffffffffu

__device__ float  g_pstate[PMAX * D];   // stores h = p/2
__device__ float  g_nstate[NMAX * D];   // stores h = p/2
__device__ float  g_Ap[PMAX * D];
__device__ float  g_G[2 * D];
__device__ float  g_consts[4];
__device__ float2 g_table[TBLN];
__device__ int    g_prog_p, g_prog_n, g_cflag, g_apcnt;

__device__ __forceinline__ float silu_f(float v) {
    return __fdividef(v, 1.0f + __expf(-v));
}
__device__ __forceinline__ float tanhf_approx(float x) {
    float r; asm("tanh.approx.f32 %0, %1;" : "=f"(r) : "f"(x)); return r;
}
__device__ __forceinline__ unsigned long long pack2(float lo, float hi) {
    unsigned long long r;
    asm("mov.b64 %0, {%1, %2};" : "=l"(r) : "f"(lo), "f"(hi));
    return r;
}
__device__ __forceinline__ void unpack2(unsigned long long v, float& lo, float& hi) {
    asm("mov.b64 {%0, %1}, %2;" : "=f"(lo), "=f"(hi) : "l"(v));
}
__device__ __forceinline__ unsigned long long fma2(unsigned long long a,
                                                   unsigned long long b,
                                                   unsigned long long c) {
    unsigned long long d;
    asm("fma.rn.f32x2 %0, %1, %2, %3;" : "=l"(d) : "l"(a), "l"(b), "l"(c));
    return d;
}
__device__ __forceinline__ unsigned long long add2(unsigned long long a,
                                                   unsigned long long b) {
    unsigned long long d;
    asm("add.rn.f32x2 %0, %1, %2;" : "=l"(d) : "l"(a), "l"(b));
    return d;
}
__device__ __forceinline__ void sts_vol(unsigned addr, float v) {
    asm volatile("st.volatile.shared.f32 [%0], %1;" :: "r"(addr), "f"(v) : "memory");
}
__device__ __forceinline__ void lds_vol_2u64(unsigned addr,
                                             unsigned long long& a,
                                             unsigned long long& b) {
    asm volatile("ld.volatile.shared.v2.u64 {%0, %1}, [%2];"
                 : "=l"(a), "=l"(b) : "r"(addr) : "memory");
}
__device__ __forceinline__ void stg_vol(float* a, float v) {
    asm volatile("st.volatile.global.f32 [%0], %1;" :: "l"(a), "f"(v) : "memory");
}
__device__ __forceinline__ float4 ldg_vol4(const float* a) {
    float4 r;
    asm volatile("ld.volatile.global.v4.f32 {%0,%1,%2,%3}, [%4];"
                 : "=f"(r.x), "=f"(r.y), "=f"(r.z), "=f"(r.w) : "l"(a) : "memory");
    return r;
}
__device__ __forceinline__ int ldg_vol_i(const int* a) {
    int r;
    asm volatile("ld.volatile.global.s32 %0, [%1];" : "=r"(r) : "l"(a) : "memory");
    return r;
}
__device__ __forceinline__ void stg_vol_i(int* a, int v) {
    asm volatile("st.volatile.global.s32 [%0], %1;" :: "l"(a), "r"(v) : "memory");
}

// ---------------------------------------------------------------------------
// Fused kernel. grid = 1+WBLKS, block 128.
//   block 0:  wid2 = proton chain, wid3 = neutron chain, wid0 = constants
//   blocks 1..WBLKS: progressive projection + pair-table columns, polling
//     chain progress via L2 (moderate pressure, spread addresses).
// Chain carry is h = p/2 (W, b pre-scaled by 0.5):
//   silu(p) = h + h*tanh(h)  — ONE MUFU on the critical path.
// Projection weights absorb the 2x (w = 2*W1).
// ---------------------------------------------------------------------------
__global__ void __launch_bounds__(128, 1)
fused_kernel(const float* __restrict__ emb,
             const float* __restrict__ Wp, const float* __restrict__ bp,
             const float* __restrict__ Wn, const float* __restrict__ bn,
             const float* __restrict__ W1, const float* __restrict__ b1,
             const float* __restrict__ ln_g, const float* __restrict__ ln_b,
             const float* __restrict__ W2, const float* __restrict__ b2,
             const float* __restrict__ Wr, const float* __restrict__ br)
{
    const int wid  = threadIdx.x >> 5;
    const int lane = threadIdx.x & 31;

    if (blockIdx.x == 0) {
        __shared__ __align__(16) float sbuf[2][2][D];

        if (wid >= 2) {
            // ------------------ serial chain (wid2=proton, wid3=neutron) ----
            const int    c    = wid - 2;
            const float* W    = (c == 0) ? Wp : Wn;
            const float* bias = (c == 0) ? bp : bn;
            const int    len  = (c == 0) ? PMAX : NMAX;
            float*       gst  = (c == 0) ? g_pstate : g_nstate;
            int*         prog = (c == 0) ? &g_prog_p : &g_prog_n;

            unsigned long long wq[16];
            #pragma unroll
            for (int k = 0; k < 16; k++)
                wq[k] = pack2(0.5f * W[lane * D + 2 * k],
                              0.5f * W[lane * D + 2 * k + 1]);
            const unsigned long long bq   = pack2(0.5f * bias[lane], 0.0f);
            const unsigned long long zero = pack2(0.0f, 0.0f);

            const unsigned sb0 = (unsigned)__cvta_generic_to_shared(&sbuf[c][0][0]);
            const unsigned sb1 = (unsigned)__cvta_generic_to_shared(&sbuf[c][1][0]);

            float h = 0.5f * emb[c * D + lane];   // h = p/2

            for (int s = 0; s < len; s++) {
                const unsigned sb = (s & 1) ? sb1 : sb0;

                // silu(p) = h + h*tanh(h)
                const float t  = tanhf_approx(h);
                const float sp = fmaf(h, t, h);

                sts_vol(sb + lane * 4, sp);

                unsigned long long q0a, q0b, q1a, q1b, q2a, q2b, q3a, q3b;
                unsigned long long q4a, q4b, q5a, q5b, q6a, q6b, q7a, q7b;
                lds_vol_2u64(sb +   0, q0a, q0b);
                lds_vol_2u64(sb +  16, q1a, q1b);
                lds_vol_2u64(sb +  32, q2a, q2b);
                lds_vol_2u64(sb +  48, q3a, q3b);
                lds_vol_2u64(sb +  64, q4a, q4b);
                lds_vol_2u64(sb +  80, q5a, q5b);
                lds_vol_2u64(sb +  96, q6a, q6b);
                lds_vol_2u64(sb + 112, q7a, q7b);

                unsigned long long a0 = fma2(wq[0],  q0a, bq);
                unsigned long long a1 = fma2(wq[2],  q1a, zero);
                unsigned long long a2 = fma2(wq[4],  q2a, zero);
                unsigned long long a3 = fma2(wq[6],  q3a, zero);
                unsigned long long a4 = fma2(wq[8],  q4a, zero);
                unsigned long long a5 = fma2(wq[10], q5a, zero);
                unsigned long long a6 = fma2(wq[12], q6a, zero);
                unsigned long long a7 = fma2(wq[14], q7a, zero);

                a0 = fma2(wq[1],  q0b, a0);
                a1 = fma2(wq[3],  q1b, a1);
                a2 = fma2(wq[5],  q2b, a2);
                a3 = fma2(wq[7],  q3b, a3);
                a4 = fma2(wq[9],  q4b, a4);
                a5 = fma2(wq[11], q5b, a5);
                a6 = fma2(wq[13], q6b, a6);
                a7 = fma2(wq[15], q7b, a7);

                const unsigned long long c0 = add2(add2(a0, a1), add2(a2, a3));
                const unsigned long long c1 = add2(add2(a4, a5), add2(a6, a7));
                float lo, hi;
                unpack2(add2(c0, c1), lo, hi);
                h = lo + hi;                      // new h = p_next / 2

                stg_vol(&gst[s * D + lane], h);

                // progress published LAGGED by 8 steps (covers store skew)
                if ((s & 7) == 7 && lane == 0 && s >= 15)
                    stg_vol_i(prog, s - 7);
            }
            __threadfence();
            if (lane == 0) stg_vol_i(prog, len);
        }
        else if (wid == 0) {
            // ------------------ fused tail constants ------------------
            const int t = lane;
            float m0 = 0.f, m1 = 0.f;
            #pragma unroll
            for (int u = 0; u < D; u++) {
                const float w2 = W2[u * D + t];
                m0 = fmaf(Wr[u],     w2, m0);
                m1 = fmaf(Wr[D + u], w2, m1);
            }
            const float g  = ln_g[t];
            const float lb = ln_b[t];
            g_G[t]     = m0 * g;
            g_G[D + t] = m1 * g;

            float sG0 = m0 * g;
            float sG1 = m1 * g;
            float d0  = fmaf(m0, lb, Wr[t]     * b2[t]);
            float d1  = fmaf(m1, lb, Wr[D + t] * b2[t]);
            #pragma unroll
            for (int off = 16; off > 0; off >>= 1) {
                sG0 += __shfl_xor_sync(FULL, sG0, off);
                sG1 += __shfl_xor_sync(FULL, sG1, off);
                d0  += __shfl_xor_sync(FULL, d0,  off);
                d1  += __shfl_xor_sync(FULL, d1,  off);
            }
            if (lane == 0) {
                g_consts[0] = sG0;
                g_consts[1] = sG1;
                g_consts[2] = d0 + br[0];
                g_consts[3] = d1 + br[1];
            }
            __threadfence();
            if (lane == 0) stg_vol_i(&g_cflag, 1);
        }
        return;
    }

    // =======================================================================
    // Worker blocks
    // =======================================================================
    __shared__ __align__(16) float wb[4][D];   // per-warp An_j broadcast

    const int gw = (blockIdx.x - 1) * 4 + wid;   // 0 .. NWARPS-1

    if (gw < PMAX) {
        // ---- proton projection: row r = gw  (states hold h = p/2 -> 2x W1) --
        const int r = gw;
        float w[D];
        #pragma unroll
        for (int j = 0; j < D; j++) w[j] = 2.0f * W1[lane * (2 * D) + j];
        const float bias = b1[lane];

        while (ldg_vol_i(&g_prog_p) <= r) __nanosleep(128);
        __threadfence();

        const float* row = &g_pstate[r * D];
        float acc = bias;
        #pragma unroll
        for (int q = 0; q < 8; q++) {
            const float4 xv = ldg_vol4(row + 4 * q);
            acc = fmaf(w[4 * q + 0], xv.x, acc);
            acc = fmaf(w[4 * q + 1], xv.y, acc);
            acc = fmaf(w[4 * q + 2], xv.z, acc);
            acc = fmaf(w[4 * q + 3], xv.w, acc);
        }
        stg_vol(&g_Ap[r * D + lane], acc);
        __threadfence();
        if (lane == 0) atomicAdd(&g_apcnt, 1);
    }
    else if (gw < PMAX + NMAX) {
        // ---- neutron projection + pair column j  (2x W1 for h-states) ----
        const int j = gw - PMAX;
        float w[D];
        #pragma unroll
        for (int jj = 0; jj < D; jj++)
            w[jj] = 2.0f * W1[lane * (2 * D) + D + jj];

        while (ldg_vol_i(&g_prog_n) <= j) __nanosleep(128);
        __threadfence();

        const float* row = &g_nstate[j * D];
        float acc = 0.0f;
        #pragma unroll
        for (int q = 0; q < 8; q++) {
            const float4 xv = ldg_vol4(row + 4 * q);
            acc = fmaf(w[4 * q + 0], xv.x, acc);
            acc = fmaf(w[4 * q + 1], xv.y, acc);
            acc = fmaf(w[4 * q + 2], xv.z, acc);
            acc = fmaf(w[4 * q + 3], xv.w, acc);
        }
        wb[wid][lane] = acc;
        __syncwarp();

        // wait for constants and the full Ap matrix
        while (ldg_vol_i(&g_cflag) == 0)   __nanosleep(128);
        while (ldg_vol_i(&g_apcnt) < PMAX) __nanosleep(128);
        __threadfence();

        float4 gq[8], hq[8];
        #pragma unroll
        for (int q = 0; q < 8; q++) {
            gq[q] = ldg_vol4(&g_G[4 * q]);
            hq[q] = ldg_vol4(&g_G[D + 4 * q]);
        }
        const float4 cc = ldg_vol4(&g_consts[0]);  // sG0, sG1, d0, d1

        const float4* an4 = (const float4*)wb[wid];

        for (int i = lane; i < PMAX; i += 32) {
            const float* ap = &g_Ap[i * D];
            float r0 = 0.f, r1 = 0.f, r2 = 0.f, r3 = 0.f;
            #pragma unroll
            for (int q = 0; q < 8; q++) {
                const float4 a = ldg_vol4(ap + 4 * q);
                const float4 n = an4[q];
                {
                    const float s = silu_f(a.x + n.x);
                    r0 += s; r1 = fmaf(s, s, r1);
                    r2 = fmaf(gq[q].x, s, r2); r3 = fmaf(hq[q].x, s, r3);
                }
                {
                    const float s = silu_f(a.y + n.y);
                    r0 += s; r1 = fmaf(s, s, r1);
                    r2 = fmaf(gq[q].y, s, r2); r3 = fmaf(hq[q].y, s, r3);
                }
                {
                    const float s = silu_f(a.z + n.z);
                    r0 += s; r1 = fmaf(s, s, r1);
                    r2 = fmaf(gq[q].z, s, r2); r3 = fmaf(hq[q].z, s, r3);
                }
                {
                    const float s = silu_f(a.w + n.w);
                    r0 += s; r1 = fmaf(s, s, r1);
                    r2 = fmaf(gq[q].w, s, r2); r3 = fmaf(hq[q].w, s, r3);
                }
            }
            const float mu  = r0 * (1.0f / D);
            const float var = r1 * (1.0f / D) - mu * mu;
            const float rs  = rsqrtf(var + 1e-5f);
            const float o0  = rs * (r2 - mu * cc.x) + cc.z;
            const float o1  = rs * (r3 - mu * cc.y) + cc.w;
            g_table[i * NMAX + j] = make_float2(o0, o1);
        }
    }
}

// ---------------------------------------------------------------------------
// Gather: direct, 2 independent int4 per thread (coalesced halves).
// ---------------------------------------------------------------------------
__global__ void gather_kernel(const int4* __restrict__ x4,
                              float4* __restrict__ out4, int H)
{
    const int t = blockIdx.x * blockDim.x + threadIdx.x;
    if (t >= H) return;

    const int4 v0 = __ldcs(x4 + t);
    const int4 v1 = __ldcs(x4 + t + H);

    const float2 a0 = g_table[(v0.x - 1) * NMAX + (v0.y - 1)];
    const float2 b0 = g_table[(v0.z - 1) * NMAX + (v0.w - 1)];
    const float2 a1 = g_table[(v1.x - 1) * NMAX + (v1.y - 1)];
    const float2 b1 = g_table[(v1.z - 1) * NMAX + (v1.w - 1)];

    __stcs(out4 + t,     make_float4(a0.x, a0.y, b0.x, b0.y));
    __stcs(out4 + t + H, make_float4(a1.x, a1.y, b1.x, b1.y));
}

// covers int4 elements in [start4, n4) plus any odd trailing int2
__global__ void gather_tail_kernel(const int4* __restrict__ x4,
                                   float4* __restrict__ out4,
                                   int start4, int n4,
                                   const int2* __restrict__ x2,
                                   float2* __restrict__ out2, int B)
{
    const int t = start4 + blockIdx.x * blockDim.x + threadIdx.x;
    if (t < n4) {
        const int4 v = x4[t];
        const float2 a = g_table[(v.x - 1) * NMAX + (v.y - 1)];
        const float2 b = g_table[(v.z - 1) * NMAX + (v.w - 1)];
        out4[t] = make_float4(a.x, a.y, b.x, b.y);
    }
    if (blockIdx.x == 0 && threadIdx.x == 0 && (B & 1)) {
        const int2 v = x2[B - 1];
        out2[B - 1] = g_table[(v.x - 1) * NMAX + (v.y - 1)];
    }
}

// ---------------------------------------------------------------------------
extern "C" void kernel_launch(void* const* d_in, const int* in_sizes, int n_in,
                              void* d_out, int out_size)
{
    const int*   x    = (const int*)  d_in[0];
    const float* emb  = (const float*)d_in[1];
    const float* Wp   = (const float*)d_in[2];
    const float* bp   = (const float*)d_in[3];
    const float* Wn   = (const float*)d_in[4];
    const float* bn   = (const float*)d_in[5];
    const float* W1   = (const float*)d_in[6];
    const float* b1   = (const float*)d_in[7];
    const float* ln_g = (const float*)d_in[8];
    const float* ln_b = (const float*)d_in[9];
    const float* W2   = (const float*)d_in[10];
    const float* b2   = (const float*)d_in[11];
    const float* Wr   = (const float*)d_in[12];
    const float* br   = (const float*)d_in[13];

    const int B  = in_sizes[0] / 2;   // x is [B, 2]

    fused_kernel<<<1 + WBLKS, 128>>>(emb, Wp, bp, Wn, bn, W1, b1,
                                     ln_g, ln_b, W2, b2, Wr, br);

    {
        const int n4 = B / 2;          // int4 elements (2 batch elems each)
        const int H  = n4 / 2;         // 2 int4 per thread
        if (H > 0) {
            const int blocks = (H + 255) / 256;
            gather_kernel<<<blocks, 256>>>((const int4*)x, (float4*)d_out, H);
        }
        const int done4 = 2 * H;
        if (done4 < n4 || (B & 1)) {
            const int rem = (n4 - done4) > 0 ? (n4 - done4) : 1;
            gather_tail_kernel<<<(rem + 255) / 256, 256>>>(
                (const int4*)x, (float4*)d_out, done4, n4,
                (const int2*)x, (float2*)d_out, B);
        }
    }
}

// round 17
// speedup vs baseline: 1.6760x; 1.6760x over previous
#include <cuda_runtime.h>
#include <cuda_bf16.h>

#define PMAX 118
#define NMAX 236
#define D 32
#define TBLN (PMAX * NMAX)          // 27848 pairs
#define WBLKS 96
#define NWARPS (WBLKS * 4)
#define FULL 0xffffffffu

__device__ float  g_pstate[PMAX * D];   // stores h = p/2
__device__ float  g_nstate[NMAX * D];   // stores h = p/2
__device__ float  g_Ap[PMAX * D];
__device__ float  g_G[2 * D];
__device__ float  g_consts[4];
__device__ float2 g_table[TBLN];
__device__ int    g_prog_p, g_prog_n, g_cflag, g_apcnt;

__device__ __forceinline__ float silu_f(float v) {
    return __fdividef(v, 1.0f + __expf(-v));
}
__device__ __forceinline__ float tanhf_approx(float x) {
    float r; asm("tanh.approx.f32 %0, %1;" : "=f"(r) : "f"(x)); return r;
}
__device__ __forceinline__ unsigned long long pack2(float lo, float hi) {
    unsigned long long r;
    asm("mov.b64 %0, {%1, %2};" : "=l"(r) : "f"(lo), "f"(hi));
    return r;
}
__device__ __forceinline__ void unpack2(unsigned long long v, float& lo, float& hi) {
    asm("mov.b64 {%0, %1}, %2;" : "=f"(lo), "=f"(hi) : "l"(v));
}
__device__ __forceinline__ unsigned long long fma2(unsigned long long a,
                                                   unsigned long long b,
                                                   unsigned long long c) {
    unsigned long long d;
    asm("fma.rn.f32x2 %0, %1, %2, %3;" : "=l"(d) : "l"(a), "l"(b), "l"(c));
    return d;
}
__device__ __forceinline__ unsigned long long add2(unsigned long long a,
                                                   unsigned long long b) {
    unsigned long long d;
    asm("add.rn.f32x2 %0, %1, %2;" : "=l"(d) : "l"(a), "l"(b));
    return d;
}
__device__ __forceinline__ void sts_vol(unsigned addr, float v) {
    asm volatile("st.volatile.shared.f32 [%0], %1;" :: "r"(addr), "f"(v) : "memory");
}
__device__ __forceinline__ void lds_vol_2u64(unsigned addr,
                                             unsigned long long& a,
                                             unsigned long long& b) {
    asm volatile("ld.volatile.shared.v2.u64 {%0, %1}, [%2];"
                 : "=l"(a), "=l"(b) : "r"(addr) : "memory");
}
__device__ __forceinline__ void stg_vol(float* a, float v) {
    asm volatile("st.volatile.global.f32 [%0], %1;" :: "l"(a), "f"(v) : "memory");
}
__device__ __forceinline__ float4 ldg_vol4(const float* a) {
    float4 r;
    asm volatile("ld.volatile.global.v4.f32 {%0,%1,%2,%3}, [%4];"
                 : "=f"(r.x), "=f"(r.y), "=f"(r.z), "=f"(r.w) : "l"(a) : "memory");
    return r;
}
__device__ __forceinline__ int ldg_vol_i(const int* a) {
    int r;
    asm volatile("ld.volatile.global.s32 %0, [%1];" : "=r"(r) : "l"(a) : "memory");
    return r;
}
__device__ __forceinline__ void stg_vol_i(int* a, int v) {
    asm volatile("st.volatile.global.s32 [%0], %1;" :: "l"(a), "r"(v) : "memory");
}

// ---------------------------------------------------------------------------
// Fused kernel. grid = 1+WBLKS, block 128.
//   block 0:  wid2 = proton chain, wid3 = neutron chain, wid0 = constants
//   blocks 1..WBLKS: progressive projection + pair-table columns, polling
//     chain progress via L2 (moderate pressure, spread addresses).
// Chain carry is h = p/2 (W, b pre-scaled by 0.5):
//   silu(p) = h + h*tanh(h)  — ONE MUFU on the critical path.
// Projection weights absorb the 2x (w = 2*W1).
// ---------------------------------------------------------------------------
__global__ void __launch_bounds__(128, 1)
fused_kernel(const float* __restrict__ emb,
             const float* __restrict__ Wp, const float* __restrict__ bp,
             const float* __restrict__ Wn, const float* __restrict__ bn,
             const float* __restrict__ W1, const float* __restrict__ b1,
             const float* __restrict__ ln_g, const float* __restrict__ ln_b,
             const float* __restrict__ W2, const float* __restrict__ b2,
             const float* __restrict__ Wr, const float* __restrict__ br)
{
    const int wid  = threadIdx.x >> 5;
    const int lane = threadIdx.x & 31;

    if (blockIdx.x == 0) {
        __shared__ __align__(16) float sbuf[2][2][D];

        if (wid >= 2) {
            // ------------------ serial chain (wid2=proton, wid3=neutron) ----
            const int    c    = wid - 2;
            const float* W    = (c == 0) ? Wp : Wn;
            const float* bias = (c == 0) ? bp : bn;
            const int    len  = (c == 0) ? PMAX : NMAX;
            float*       gst  = (c == 0) ? g_pstate : g_nstate;
            int*         prog = (c == 0) ? &g_prog_p : &g_prog_n;

            unsigned long long wq[16];
            #pragma unroll
            for (int k = 0; k < 16; k++)
                wq[k] = pack2(0.5f * W[lane * D + 2 * k],
                              0.5f * W[lane * D + 2 * k + 1]);
            const unsigned long long bq   = pack2(0.5f * bias[lane], 0.0f);
            const unsigned long long zero = pack2(0.0f, 0.0f);

            const unsigned sb0 = (unsigned)__cvta_generic_to_shared(&sbuf[c][0][0]);
            const unsigned sb1 = (unsigned)__cvta_generic_to_shared(&sbuf[c][1][0]);

            float h = 0.5f * emb[c * D + lane];   // h = p/2

            for (int s = 0; s < len; s++) {
                const unsigned sb = (s & 1) ? sb1 : sb0;

                // silu(p) = h + h*tanh(h)
                const float t  = tanhf_approx(h);
                const float sp = fmaf(h, t, h);

                sts_vol(sb + lane * 4, sp);

                unsigned long long q0a, q0b, q1a, q1b, q2a, q2b, q3a, q3b;
                unsigned long long q4a, q4b, q5a, q5b, q6a, q6b, q7a, q7b;
                lds_vol_2u64(sb +   0, q0a, q0b);
                lds_vol_2u64(sb +  16, q1a, q1b);
                lds_vol_2u64(sb +  32, q2a, q2b);
                lds_vol_2u64(sb +  48, q3a, q3b);
                lds_vol_2u64(sb +  64, q4a, q4b);
                lds_vol_2u64(sb +  80, q5a, q5b);
                lds_vol_2u64(sb +  96, q6a, q6b);
                lds_vol_2u64(sb + 112, q7a, q7b);

                unsigned long long a0 = fma2(wq[0],  q0a, bq);
                unsigned long long a1 = fma2(wq[2],  q1a, zero);
                unsigned long long a2 = fma2(wq[4],  q2a, zero);
                unsigned long long a3 = fma2(wq[6],  q3a, zero);
                unsigned long long a4 = fma2(wq[8],  q4a, zero);
                unsigned long long a5 = fma2(wq[10], q5a, zero);
                unsigned long long a6 = fma2(wq[12], q6a, zero);
                unsigned long long a7 = fma2(wq[14], q7a, zero);

                a0 = fma2(wq[1],  q0b, a0);
                a1 = fma2(wq[3],  q1b, a1);
                a2 = fma2(wq[5],  q2b, a2);
                a3 = fma2(wq[7],  q3b, a3);
                a4 = fma2(wq[9],  q4b, a4);
                a5 = fma2(wq[11], q5b, a5);
                a6 = fma2(wq[13], q6b, a6);
                a7 = fma2(wq[15], q7b, a7);

                const unsigned long long c0 = add2(add2(a0, a1), add2(a2, a3));
                const unsigned long long c1 = add2(add2(a4, a5), add2(a6, a7));
                float lo, hi;
                unpack2(add2(c0, c1), lo, hi);
                h = lo + hi;                      // new h = p_next / 2

                stg_vol(&gst[s * D + lane], h);

                // progress published LAGGED by 8 steps (covers store skew)
                if ((s & 7) == 7 && lane == 0 && s >= 15)
                    stg_vol_i(prog, s - 7);
            }
            __threadfence();
            if (lane == 0) stg_vol_i(prog, len);
        }
        else if (wid == 0) {
            // ------------------ fused tail constants ------------------
            const int t = lane;
            float m0 = 0.f, m1 = 0.f;
            #pragma unroll
            for (int u = 0; u < D; u++) {
                const float w2 = W2[u * D + t];
                m0 = fmaf(Wr[u],     w2, m0);
                m1 = fmaf(Wr[D + u], w2, m1);
            }
            const float g  = ln_g[t];
            const float lb = ln_b[t];
            g_G[t]     = m0 * g;
            g_G[D + t] = m1 * g;

            float sG0 = m0 * g;
            float sG1 = m1 * g;
            float d0  = fmaf(m0, lb, Wr[t]     * b2[t]);
            float d1  = fmaf(m1, lb, Wr[D + t] * b2[t]);
            #pragma unroll
            for (int off = 16; off > 0; off >>= 1) {
                sG0 += __shfl_xor_sync(FULL, sG0, off);
                sG1 += __shfl_xor_sync(FULL, sG1, off);
                d0  += __shfl_xor_sync(FULL, d0,  off);
                d1  += __shfl_xor_sync(FULL, d1,  off);
            }
            if (lane == 0) {
                g_consts[0] = sG0;
                g_consts[1] = sG1;
                g_consts[2] = d0 + br[0];
                g_consts[3] = d1 + br[1];
            }
            __threadfence();
            if (lane == 0) stg_vol_i(&g_cflag, 1);
        }
        return;
    }

    // =======================================================================
    // Worker blocks
    // =======================================================================
    __shared__ __align__(16) float wb[4][D];   // per-warp An_j broadcast

    const int gw = (blockIdx.x - 1) * 4 + wid;   // 0 .. NWARPS-1

    if (gw < PMAX) {
        // ---- proton projection: row r = gw  (states hold h = p/2 -> 2x W1) --
        const int r = gw;
        float w[D];
        #pragma unroll
        for (int j = 0; j < D; j++) w[j] = 2.0f * W1[lane * (2 * D) + j];
        const float bias = b1[lane];

        while (ldg_vol_i(&g_prog_p) <= r) __nanosleep(128);
        __threadfence();

        const float* row = &g_pstate[r * D];
        float acc = bias;
        #pragma unroll
        for (int q = 0; q < 8; q++) {
            const float4 xv = ldg_vol4(row + 4 * q);
            acc = fmaf(w[4 * q + 0], xv.x, acc);
            acc = fmaf(w[4 * q + 1], xv.y, acc);
            acc = fmaf(w[4 * q + 2], xv.z, acc);
            acc = fmaf(w[4 * q + 3], xv.w, acc);
        }
        stg_vol(&g_Ap[r * D + lane], acc);
        __threadfence();
        if (lane == 0) atomicAdd(&g_apcnt, 1);
    }
    else if (gw < PMAX + NMAX) {
        // ---- neutron projection + pair column j  (2x W1 for h-states) ----
        const int j = gw - PMAX;
        float w[D];
        #pragma unroll
        for (int jj = 0; jj < D; jj++)
            w[jj] = 2.0f * W1[lane * (2 * D) + D + jj];

        while (ldg_vol_i(&g_prog_n) <= j) __nanosleep(128);
        __threadfence();

        const float* row = &g_nstate[j * D];
        float acc = 0.0f;
        #pragma unroll
        for (int q = 0; q < 8; q++) {
            const float4 xv = ldg_vol4(row + 4 * q);
            acc = fmaf(w[4 * q + 0], xv.x, acc);
            acc = fmaf(w[4 * q + 1], xv.y, acc);
            acc = fmaf(w[4 * q + 2], xv.z, acc);
            acc = fmaf(w[4 * q + 3], xv.w, acc);
        }
        wb[wid][lane] = acc;
        __syncwarp();

        // wait for constants and the full Ap matrix
        while (ldg_vol_i(&g_cflag) == 0)   __nanosleep(128);
        while (ldg_vol_i(&g_apcnt) < PMAX) __nanosleep(128);
        __threadfence();

        float4 gq[8], hq[8];
        #pragma unroll
        for (int q = 0; q < 8; q++) {
            gq[q] = ldg_vol4(&g_G[4 * q]);
            hq[q] = ldg_vol4(&g_G[D + 4 * q]);
        }
        const float4 cc = ldg_vol4(&g_consts[0]);  // sG0, sG1, d0, d1

        const float4* an4 = (const float4*)wb[wid];

        for (int i = lane; i < PMAX; i += 32) {
            const float* ap = &g_Ap[i * D];
            float r0 = 0.f, r1 = 0.f, r2 = 0.f, r3 = 0.f;
            #pragma unroll
            for (int q = 0; q < 8; q++) {
                const float4 a = ldg_vol4(ap + 4 * q);
                const float4 n = an4[q];
                {
                    const float s = silu_f(a.x + n.x);
                    r0 += s; r1 = fmaf(s, s, r1);
                    r2 = fmaf(gq[q].x, s, r2); r3 = fmaf(hq[q].x, s, r3);
                }
                {
                    const float s = silu_f(a.y + n.y);
                    r0 += s; r1 = fmaf(s, s, r1);
                    r2 = fmaf(gq[q].y, s, r2); r3 = fmaf(hq[q].y, s, r3);
                }
                {
                    const float s = silu_f(a.z + n.z);
                    r0 += s; r1 = fmaf(s, s, r1);
                    r2 = fmaf(gq[q].z, s, r2); r3 = fmaf(hq[q].z, s, r3);
                }
                {
                    const float s = silu_f(a.w + n.w);
                    r0 += s; r1 = fmaf(s, s, r1);
                    r2 = fmaf(gq[q].w, s, r2); r3 = fmaf(hq[q].w, s, r3);
                }
            }
            const float mu  = r0 * (1.0f / D);
            const float var = r1 * (1.0f / D) - mu * mu;
            const float rs  = rsqrtf(var + 1e-5f);
            const float o0  = rs * (r2 - mu * cc.x) + cc.z;
            const float o1  = rs * (r3 - mu * cc.y) + cc.w;
            g_table[i * NMAX + j] = make_float2(o0, o1);
        }
    }
}

// ---------------------------------------------------------------------------
// Gather: direct, 2 independent int4 per thread (coalesced halves).
// ---------------------------------------------------------------------------
__global__ void gather_kernel(const int4* __restrict__ x4,
                              float4* __restrict__ out4, int H)
{
    const int t = blockIdx.x * blockDim.x + threadIdx.x;
    if (t >= H) return;

    const int4 v0 = __ldcs(x4 + t);
    const int4 v1 = __ldcs(x4 + t + H);

    const float2 a0 = g_table[(v0.x - 1) * NMAX + (v0.y - 1)];
    const float2 b0 = g_table[(v0.z - 1) * NMAX + (v0.w - 1)];
    const float2 a1 = g_table[(v1.x - 1) * NMAX + (v1.y - 1)];
    const float2 b1 = g_table[(v1.z - 1) * NMAX + (v1.w - 1)];

    __stcs(out4 + t,     make_float4(a0.x, a0.y, b0.x, b0.y));
    __stcs(out4 + t + H, make_float4(a1.x, a1.y, b1.x, b1.y));
}

// covers int4 elements in [start4, n4) plus any odd trailing int2
__global__ void gather_tail_kernel(const int4* __restrict__ x4,
                                   float4* __restrict__ out4,
                                   int start4, int n4,
                                   const int2* __restrict__ x2,
                                   float2* __restrict__ out2, int B)
{
    const int t = start4 + blockIdx.x * blockDim.x + threadIdx.x;
    if (t < n4) {
        const int4 v = x4[t];
        const float2 a = g_table[(v.x - 1) * NMAX + (v.y - 1)];
        const float2 b = g_table[(v.z - 1) * NMAX + (v.w - 1)];
        out4[t] = make_float4(a.x, a.y, b.x, b.y);
    }
    if (blockIdx.x == 0 && threadIdx.x == 0 && (B & 1)) {
        const int2 v = x2[B - 1];
        out2[B - 1] = g_table[(v.x - 1) * NMAX + (v.y - 1)];
    }
}

// ---------------------------------------------------------------------------
extern "C" void kernel_launch(void* const* d_in, const int* in_sizes, int n_in,
                              void* d_out, int out_size)
{
    const int*   x    = (const int*)  d_in[0];
    const float* emb  = (const float*)d_in[1];
    const float* Wp   = (const float*)d_in[2];
    const float* bp   = (const float*)d_in[3];
    const float* Wn   = (const float*)d_in[4];
    const float* bn   = (const float*)d_in[5];
    const float* W1   = (const float*)d_in[6];
    const float* b1   = (const float*)d_in[7];
    const float* ln_g = (const float*)d_in[8];
    const float* ln_b = (const float*)d_in[9];
    const float* W2   = (const float*)d_in[10];
    const float* b2   = (const float*)d_in[11];
    const float* Wr   = (const float*)d_in[12];
    const float* br   = (const float*)d_in[13];

    const int B  = in_sizes[0] / 2;   // x is [B, 2]

    fused_kernel<<<1 + WBLKS, 128>>>(emb, Wp, bp, Wn, bn, W1, b1,
                                     ln_g, ln_b, W2, b2, Wr, br);

    {
        const int n4 = B / 2;          // int4 elements (2 batch elems each)
        const int H  = n4 / 2;         // 2 int4 per thread
        if (H > 0) {
            const int blocks = (H + 255) / 256;
            gather_kernel<<<blocks, 256>>>((const int4*)x, (float4*)d_out, H);
        }
        const int done4 = 2 * H;
        if (done4 < n4 || (B & 1)) {
            const int rem = (n4 - done4) > 0 ? (n4 - done4) : 1;
            gather_tail_kernel<<<(rem + 255) / 256, 256>>>(
                (const int4*)x, (float4*)d_out, done4, n4,
                (const int2*)x, (float2*)d_out, B);
        }
    }
}